// round 15
// baseline (speedup 1.0000x reference)
#include <cuda_runtime.h>
#include <math.h>
#include <stdint.h>

// ---------------------------------------------------------------------------
// LSTM + differentiable stack, 259 steps, persistent kernel, 128 CTAs x 256 thr.
// GEMM tile (proven R12): 4 cols x 8 batches x 4-way k-split FFMA2 at pipe floor.
// R14: 3-buffer TMA ring with depth-2 prefetch in I1 (steady-state TMA hidden).
// smem found by aliasing phase-disjoint scratch (srr/so/sred) inside gs.
//  I1: gates h-part (8 x 64k chunks, ring-of-3) + fused f32x2 readout o194_t.
//  I2: CTA b: V store, sp/sA (scan precomputed in prior I3), gather -> r_t.
//      x_{t+1} TMAs (slots 2,0) issued at I2 start; x0 GEMM pre-barrier.
//  I3: softmax + next-step scan (overlap r TMA) + x1 + r + k-reduce + cell.
// Grid barrier: red.release.gpu + ld.acquire poll.
// ---------------------------------------------------------------------------

#define BATCH   128
#define HID     512
#define INPD    128
#define STKD    64
#define MAXT    259
#define NSTEPS  259
#define KSTART  129
#define OCOLS   194
#define OPAD    208

#define GRIDN   128
#define NTHR    256
#define KCH     64
#define CHF     (KCH * BATCH)            // 8192 floats per chunk
#define CHB     (CHF * 4)                // 32768 B per chunk

// smem float offsets
#define OFF_WS   0                       // 704 x 16 scalar W (11264 f)
#define OFF_AS   11264                   // 3 x (64 x 128) A ring (24576 f)
#define OFF_V    35840                   // 259 x 64 stack V (16576 f)
#define OFF_WRD  52416                   // 1024 u64 dup Wr (2048 f)
#define OFF_GS   54464                   // 16 x 132 gate exchange (2112 f)
#define OFF_SRR  OFF_GS                  // 1024 f readout reduce   (alias, I1-tail)
#define OFF_SO   (OFF_GS + 1024)         // 208 f o194 row          (alias, I2..I3-softmax)
#define OFF_SRD  (OFF_GS + 1232)         // 256 f gather reduce     (alias, I2)
#define OFF_SC   56576                   // 512 c-state
#define OFF_SB   57088                   // 16 gate bias
#define OFF_SBR  57104                   // 2 readout bias
#define OFF_SS   57106                   // 292 stack s
#define OFF_SUF  57400                   // 288 suffix (persists I3->I2)
#define OFF_SA   57688                   // 288 A coeffs
#define OFF_CS   57976                   // 32 (persists I3->I2)
#define OFF_MB   58008                   // 3 mbarriers (24 B, 8-aligned)
#define SMEMF    58016
#define SMEMB    (SMEMF * 4)             // 232064 B (<= 227 KB)

__device__ float d_xT[129 * 128 * 128];      // x transposed [t][k][b]
__device__ float d_RH[(64 + 512) * 128];     // rows 0..63: r ; 64..575: h  ([k][b])
__device__ float d_o194[BATCH * OPAD];       // readout batch-major [b][n]
__device__ unsigned g_bar;

__device__ __forceinline__ float sigf(float x) { return 1.0f / (1.0f + expf(-x)); }

#define FFMA2(acc, a, w) \
    asm volatile("fma.rn.f32x2 %0, %1, %2, %0;" : "+l"(acc) : "l"(a), "l"(w))
#define ADDF2(acc, a) \
    asm volatile("add.rn.f32x2 %0, %0, %1;" : "+l"(acc) : "l"(a))
#define DUP2(d, s) \
    asm volatile("mov.b64 %0, {%1, %1};" : "=l"(d) : "r"(__float_as_uint(s)))

// Grid barrier: release-REDG arrival + acquire-load poll.
__device__ __forceinline__ void grid_sync(unsigned &n) {
    __syncthreads();
    n += (unsigned)GRIDN;
    if (threadIdx.x == 0) {
        asm volatile("red.release.gpu.global.add.u32 [%0], %1;"
                     :: "l"(&g_bar), "r"(1u) : "memory");
        unsigned v;
        do {
            asm volatile("ld.acquire.gpu.global.u32 %0, [%1];"
                         : "=r"(v) : "l"(&g_bar));
        } while ((int)(v - n) < 0);
    }
    __syncthreads();
}

__device__ __forceinline__ void mbar_init(uint32_t mbar) {
    asm volatile("mbarrier.init.shared.b64 [%0], %1;" :: "r"(mbar), "r"(1u) : "memory");
}
__device__ __forceinline__ void mbar_expect(uint32_t mbar, uint32_t bytes) {
    asm volatile("mbarrier.arrive.expect_tx.shared.b64 _, [%0], %1;"
                 :: "r"(mbar), "r"(bytes) : "memory");
}
__device__ __forceinline__ void bulk_ld(uint32_t dst, const float *src,
                                        uint32_t bytes, uint32_t mbar) {
    asm volatile("cp.async.bulk.shared::cluster.global.mbarrier::complete_tx::bytes "
                 "[%0], [%1], %2, [%3];"
                 :: "r"(dst), "l"(src), "r"(bytes), "r"(mbar) : "memory");
}
__device__ __forceinline__ void mbar_wait(uint32_t mbar, uint32_t parity) {
    asm volatile(
        "{\n\t.reg .pred P;\n\t"
        "WL_%=:\n\t"
        "mbarrier.try_wait.parity.acquire.cta.shared::cta.b64 P, [%0], %1, 0x989680;\n\t"
        "@P bra.uni WD_%=;\n\t"
        "bra.uni WL_%=;\n\t"
        "WD_%=:\n\t}"
        :: "r"(mbar), "r"(parity) : "memory");
}

struct Pipe {
    uint32_t mb0, as0;
    unsigned ph;
    __device__ __forceinline__ void prefetch(int s, const float *src, bool issuer) {
        if (issuer) {
            uint32_t mb = mb0 + (unsigned)s * 8u;
            mbar_expect(mb, CHB);
            bulk_ld(as0 + (unsigned)s * CHB, src, CHB, mb);
        }
    }
    __device__ __forceinline__ void wait(int s) {
        mbar_wait(mb0 + (unsigned)s * 8u, (ph >> s) & 1u);
        ph ^= (1u << s);
    }
};

__global__ void __launch_bounds__(NTHR, 1)
lstm_stack_kernel(const float *__restrict__ x,
                  const float *__restrict__ Wih, const float *__restrict__ bih,
                  const float *__restrict__ Whh, const float *__restrict__ bhh,
                  const float *__restrict__ Wr, const float *__restrict__ br,
                  float *__restrict__ out) {
    extern __shared__ __align__(16) float smf[];
    float *Ws   = smf + OFF_WS;
    float *As   = smf + OFF_AS;
    float *Vs   = smf + OFF_V;
    unsigned long long *Wrd = (unsigned long long *)(smf + OFF_WRD);
    float *gs   = smf + OFF_GS;
    float *srr  = smf + OFF_SRR;
    float *so   = smf + OFF_SO;
    float *sred = smf + OFF_SRD;
    float *sc   = smf + OFF_SC;
    float *sb   = smf + OFF_SB;
    float *sbr  = smf + OFF_SBR;
    float *ss   = smf + OFF_SS;
    float *ssuf = smf + OFF_SUF;
    float *sA   = smf + OFF_SA;
    float *csum = smf + OFF_CS;

    const int tid  = threadIdx.x;
    const int bidx = blockIdx.x;
    const int lane = tid & 31, wid = tid >> 5;
    unsigned n = 0;

    Pipe pipe;
    pipe.mb0 = (uint32_t)__cvta_generic_to_shared(smf + OFF_MB);
    pipe.as0 = (uint32_t)__cvta_generic_to_shared(As);
    pipe.ph  = 0;
    if (tid == 0) {
        mbar_init(pipe.mb0);
        mbar_init(pipe.mb0 + 8);
        mbar_init(pipe.mb0 + 16);
    }
    __syncthreads();

    // ---------------- prologue: transpose x[t] -> d_xT[t][k][b] -------------
    {
        float *tile = smf;  // 128x132 scratch inside Ws+As region (loaded later)
        for (int p = bidx; p < KSTART; p += GRIDN) {
#pragma unroll
            for (int q = 0; q < 16; ++q) {
                int idx = q * 1024 + tid * 4;
                int b = idx >> 7, k = idx & 127;
                float4 v = *(const float4 *)(x + ((size_t)p * 128 + b) * 128 + k);
                tile[b * 132 + k]     = v.x;
                tile[b * 132 + k + 1] = v.y;
                tile[b * 132 + k + 2] = v.z;
                tile[b * 132 + k + 3] = v.w;
            }
            __syncthreads();
#pragma unroll
            for (int q = 0; q < 16; ++q) {
                int idx = q * 1024 + tid * 4;
                int k = idx >> 7, b = idx & 127;
                float4 v = make_float4(tile[b * 132 + k], tile[(b + 1) * 132 + k],
                                       tile[(b + 2) * 132 + k], tile[(b + 3) * 132 + k]);
                *(float4 *)(d_xT + ((size_t)p * 128 + k) * 128 + b) = v;
            }
            __syncthreads();
        }
    }
    grid_sync(n);

    // ---------------- persistent loads ----------------
    for (int idx = tid; idx < 704 * 16; idx += NTHR) {
        int k = idx >> 4, cidx = idx & 15;
        int m = cidx >> 2, u = cidx & 3;
        int grow = m * 512 + bidx * 4 + u;
        Ws[idx] = (k < 192) ? Wih[(size_t)grow * 192 + k]
                            : Whh[(size_t)grow * 512 + (k - 192)];
    }
    for (int idx = tid; idx < 1024; idx += NTHR) {
        int c = idx >> 9, k = idx & 511;
        int nn = bidx + c * 128;
        float w = (nn < OCOLS) ? Wr[(size_t)nn * HID + k] : 0.0f;
        unsigned ub = __float_as_uint(w);
        Wrd[c * 512 + k] = (unsigned long long)ub | ((unsigned long long)ub << 32);
    }
    if (tid < 16) {
        int m = tid >> 2, u = tid & 3;
        int grow = m * 512 + bidx * 4 + u;
        sb[tid] = bih[grow] + bhh[grow];
    }
    if (tid < 2) {
        int nn = bidx + tid * 128;
        sbr[tid] = (nn < OCOLS) ? br[nn] : 0.0f;
    }
    for (int idx = tid; idx < 512; idx += NTHR) sc[idx] = 0.0f;
    for (int idx = tid; idx < 292; idx += NTHR) ss[idx] = 0.0f;
    for (int idx = tid; idx < 288; idx += NTHR) ssuf[idx] = 0.0f;  // scan of zeros
    if (tid < 32) csum[tid] = 0.0f;
    for (int idx = tid; idx < MAXT * STKD; idx += NTHR) Vs[idx] = 0.0f;
    __syncthreads();

    // GEMM thread mapping: 4 cols x 8 batches x 4-way k-split
    const int tx = tid & 3;            // col quad (cols 4tx..4tx+3)
    const int bo = (tid >> 2) & 15;    // batch octet (batches bo*8..bo*8+7)
    const int kq = tid >> 6;           // k-quarter within each 64-k chunk
    // readout mapping
    const int rc  = tid >> 7;            // col 0/1
    const int rks = (tid >> 5) & 3;      // k-split (16 kk each)
    const int rbq = tid & 31;            // batch quad

    unsigned long long acc0, acc1, acc2, acc3, acc4, acc5, acc6, acc7,
                       acc8, acc9, acc10, acc11, acc12, acc13, acc14, acc15;

#define ZERO_ACCS() \
    acc0 = acc1 = acc2 = acc3 = acc4 = acc5 = acc6 = acc7 = 0ull;   \
    acc8 = acc9 = acc10 = acc11 = acc12 = acc13 = acc14 = acc15 = 0ull;

// GEMM over one resident 64-k chunk: this thread covers its 16-k quarter.
#define GEMM_CHUNK(Ab, wrow)                                                  \
    {                                                                         \
        const float *Ab_ = (Ab) + kq * 16 * 128 + bo * 8;                     \
        const float *wp_ = Ws + (size_t)((wrow) + kq * 16) * 16 + tx * 4;     \
        _Pragma("unroll")                                                     \
        for (int kk = 0; kk < 16; ++kk) {                                     \
            ulonglong2 a01 = *(const ulonglong2 *)(Ab_ + kk * 128);           \
            ulonglong2 a23 = *(const ulonglong2 *)(Ab_ + kk * 128 + 4);       \
            float4 w = *(const float4 *)(wp_ + kk * 16);                      \
            unsigned long long w0, w1, w2, w3;                                \
            DUP2(w0, w.x); DUP2(w1, w.y); DUP2(w2, w.z); DUP2(w3, w.w);       \
            FFMA2(acc0,  a01.x, w0); FFMA2(acc1,  a01.y, w0);                 \
            FFMA2(acc2,  a23.x, w0); FFMA2(acc3,  a23.y, w0);                 \
            FFMA2(acc4,  a01.x, w1); FFMA2(acc5,  a01.y, w1);                 \
            FFMA2(acc6,  a23.x, w1); FFMA2(acc7,  a23.y, w1);                 \
            FFMA2(acc8,  a01.x, w2); FFMA2(acc9,  a01.y, w2);                 \
            FFMA2(acc10, a23.x, w2); FFMA2(acc11, a23.y, w2);                 \
            FFMA2(acc12, a01.x, w3); FFMA2(acc13, a01.y, w3);                 \
            FFMA2(acc14, a23.x, w3); FFMA2(acc15, a23.y, w3);                 \
        }                                                                     \
    }

// 4-way k-split reduce (via A buffer 0, consumed by then) + bias -> gs -> cell.
#define EPILOGUE_CELL()                                                       \
    __syncthreads();                                                          \
    {                                                                         \
        unsigned long long *red_ = (unsigned long long *)As;                  \
        const int pos_ = tid & 63;                                            \
        if (kq != 0) {                                                        \
            unsigned long long *d_ = red_ + ((size_t)(kq - 1) * 64 + pos_) * 16; \
            *(ulonglong2 *)(d_)      = make_ulonglong2(acc0,  acc1);          \
            *(ulonglong2 *)(d_ + 2)  = make_ulonglong2(acc2,  acc3);          \
            *(ulonglong2 *)(d_ + 4)  = make_ulonglong2(acc4,  acc5);          \
            *(ulonglong2 *)(d_ + 6)  = make_ulonglong2(acc6,  acc7);          \
            *(ulonglong2 *)(d_ + 8)  = make_ulonglong2(acc8,  acc9);          \
            *(ulonglong2 *)(d_ + 10) = make_ulonglong2(acc10, acc11);         \
            *(ulonglong2 *)(d_ + 12) = make_ulonglong2(acc12, acc13);         \
            *(ulonglong2 *)(d_ + 14) = make_ulonglong2(acc14, acc15);         \
        }                                                                     \
        __syncthreads();                                                      \
        if (kq == 0) {                                                        \
            _Pragma("unroll")                                                 \
            for (int s = 0; s < 3; ++s) {                                     \
                const unsigned long long *s_ = red_ + ((size_t)s * 64 + tid) * 16; \
                ADDF2(acc0,  s_[0]);  ADDF2(acc1,  s_[1]);                    \
                ADDF2(acc2,  s_[2]);  ADDF2(acc3,  s_[3]);                    \
                ADDF2(acc4,  s_[4]);  ADDF2(acc5,  s_[5]);                    \
                ADDF2(acc6,  s_[6]);  ADDF2(acc7,  s_[7]);                    \
                ADDF2(acc8,  s_[8]);  ADDF2(acc9,  s_[9]);                    \
                ADDF2(acc10, s_[10]); ADDF2(acc11, s_[11]);                   \
                ADDF2(acc12, s_[12]); ADDF2(acc13, s_[13]);                   \
                ADDF2(acc14, s_[14]); ADDF2(acc15, s_[15]);                   \
            }                                                                 \
            unsigned long long av_[16] = {acc0, acc1, acc2,  acc3,            \
                                          acc4, acc5, acc6,  acc7,            \
                                          acc8, acc9, acc10, acc11,           \
                                          acc12, acc13, acc14, acc15};        \
            _Pragma("unroll")                                                 \
            for (int c = 0; c < 4; ++c) {                                     \
                int col_ = tx * 4 + c;                                        \
                float bs_ = sb[col_];                                         \
                float *gp_ = gs + col_ * 132 + bo * 8;                        \
                unsigned long long v0_ = av_[c * 4], v1_ = av_[c * 4 + 1];    \
                unsigned long long v2_ = av_[c * 4 + 2], v3_ = av_[c * 4 + 3];\
                *(float4 *)gp_ = make_float4(                                 \
                    __uint_as_float((unsigned)v0_) + bs_,                     \
                    __uint_as_float((unsigned)(v0_ >> 32)) + bs_,             \
                    __uint_as_float((unsigned)v1_) + bs_,                     \
                    __uint_as_float((unsigned)(v1_ >> 32)) + bs_);            \
                *(float4 *)(gp_ + 4) = make_float4(                           \
                    __uint_as_float((unsigned)v2_) + bs_,                     \
                    __uint_as_float((unsigned)(v2_ >> 32)) + bs_,             \
                    __uint_as_float((unsigned)v3_) + bs_,                     \
                    __uint_as_float((unsigned)(v3_ >> 32)) + bs_);            \
            }                                                                 \
        }                                                                     \
    }                                                                         \
    __syncthreads();                                                          \
    _Pragma("unroll")                                                         \
    for (int r = 0; r < 2; ++r) {                                             \
        int idx = tid + r * NTHR;                                             \
        int u = idx >> 7, bb = idx & 127;                                     \
        float gi = gs[u * 132 + bb];                                          \
        float gf = gs[(4 + u) * 132 + bb];                                    \
        float gg = gs[(8 + u) * 132 + bb];                                    \
        float go = gs[(12 + u) * 132 + bb];                                   \
        float c2 = sigf(gf) * sc[idx] + sigf(gi) * tanhf(gg);                 \
        sc[idx] = c2;                                                         \
        d_RH[(size_t)(64 + bidx * 4 + u) * 128 + bb] = sigf(go) * tanhf(c2);  \
    }

// Suffix scan of ss -> ssuf, csum (for the NEXT step's I2).
#define SCAN_SS()                                                             \
    for (int cch = wid; cch < 9; cch += 8) {                                  \
        float v = ss[cch * 32 + lane];                                        \
        _Pragma("unroll")                                                     \
        for (int o = 1; o < 32; o <<= 1) {                                    \
            float tv = __shfl_down_sync(0xffffffffu, v, o);                   \
            if (lane + o < 32) v += tv;                                       \
        }                                                                     \
        ssuf[cch * 32 + lane] = v;                                            \
        if (lane == 0) csum[cch] = v;                                         \
    }                                                                         \
    __syncthreads();                                                          \
    if (wid == 0) {                                                           \
        float tv = (lane < 9) ? csum[lane] : 0.0f;                            \
        float vv = tv;                                                        \
        _Pragma("unroll")                                                     \
        for (int o = 1; o < 16; o <<= 1) {                                    \
            float sh = __shfl_down_sync(0xffffffffu, vv, o);                  \
            if (lane + o < 16) vv += sh;                                      \
        }                                                                     \
        if (lane < 9) csum[lane] = vv - tv;                                   \
    }

// Log-softmax of so[64..191] -> out row (t >= KSTART). Uses csum as scratch;
// must run BEFORE SCAN_SS() in the same phase.
#define SOFTMAX_OUT(tt)                                                       \
    {                                                                         \
        float v = (tid < INPD) ? so[STKD + tid] : -1e30f;                     \
        float m = v;                                                          \
        _Pragma("unroll")                                                     \
        for (int o = 16; o; o >>= 1)                                          \
            m = fmaxf(m, __shfl_xor_sync(0xffffffffu, m, o));                 \
        if (lane == 0) csum[wid] = m;                                         \
        __syncthreads();                                                      \
        float mm = csum[0];                                                   \
        _Pragma("unroll")                                                     \
        for (int w = 1; w < 8; ++w) mm = fmaxf(mm, csum[w]);                  \
        float e = (tid < INPD) ? expf(v - mm) : 0.0f;                         \
        _Pragma("unroll")                                                     \
        for (int o = 16; o; o >>= 1)                                          \
            e += __shfl_xor_sync(0xffffffffu, e, o);                          \
        if (lane == 0) csum[8 + wid] = e;                                     \
        __syncthreads();                                                      \
        float tot = 0.0f;                                                     \
        _Pragma("unroll")                                                     \
        for (int w = 0; w < 8; ++w) tot += csum[8 + w];                       \
        float ls = logf(tot);                                                 \
        if (tid < INPD)                                                       \
            out[(((size_t)((tt) - KSTART)) * BATCH + bidx) * INPD + tid] =    \
                v - mm - ls;                                                  \
        __syncthreads();                                                      \
    }

    // ================= init: gates_0 = x_0 part only; cell -> h_0 ===========
    ZERO_ACCS()
    pipe.prefetch(0, d_xT, tid == 0);
    pipe.prefetch(1, d_xT + 64 * 128, tid == 0);
    pipe.wait(0);
    GEMM_CHUNK(As, 0)
    __syncthreads();
    pipe.wait(1);
    GEMM_CHUNK(As + CHF, 64)
    EPILOGUE_CELL()
    grid_sync(n);

    // =========================== main time loop =============================
    for (int t = 0; t < NSTEPS; ++t) {
        const bool has_x = (t < 128);

        // ---------- I1: 8 h chunks, ring-of-3, depth-2 prefetch ----------
        pipe.prefetch(0, d_RH + (size_t)64 * 128, tid == 0);
        pipe.prefetch(1, d_RH + (size_t)(64 + 64) * 128, tid == 0);
        ZERO_ACCS()
        unsigned long long racc0 = 0ull, racc1 = 0ull;
#pragma unroll 1
        for (int ci = 0; ci < 8; ++ci) {
            if (ci + 2 < 8)
                pipe.prefetch((ci + 2) % 3,
                              d_RH + (size_t)(64 + (ci + 2) * 64) * 128, tid == 0);
            const int st = ci % 3;
            pipe.wait(st);
            const float *Ab = As + st * CHF;
            GEMM_CHUNK(Ab, 192 + ci * 64)
            {   // f32x2 readout over this h chunk
                const float *Ar = Ab + (rks * 16) * 128 + rbq * 4;
                const unsigned long long *wr = Wrd + rc * 512 + ci * 64 + rks * 16;
#pragma unroll
                for (int m = 0; m < 16; ++m) {
                    ulonglong2 a = *(const ulonglong2 *)(Ar + m * 128);
                    unsigned long long w = wr[m];
                    FFMA2(racc0, a.x, w);
                    FFMA2(racc1, a.y, w);
                }
            }
            __syncthreads();
        }
        // readout reduce + store o194 batch-major
        {
            float4 rv = make_float4(__uint_as_float((unsigned)racc0),
                                    __uint_as_float((unsigned)(racc0 >> 32)),
                                    __uint_as_float((unsigned)racc1),
                                    __uint_as_float((unsigned)(racc1 >> 32)));
            *(float4 *)(srr + rks * 256 + rc * 128 + rbq * 4) = rv;
        }
        __syncthreads();
        {
            int c = tid >> 7, b = tid & 127;
            int nn = bidx + c * 128;
            if (nn < OCOLS) {
                float o = srr[b + c * 128] + srr[256 + b + c * 128] +
                          srr[512 + b + c * 128] + srr[768 + b + c * 128] + sbr[c];
                d_o194[(size_t)b * OPAD + nn] = o;
            }
        }
        grid_sync(n);

        // ---------- I2: stack update for batch b = bidx (SHORT chain) -------
        // x_{t+1} TMAs: slot2 then slot0 (both consumed in I1 by now).
        if (has_x) {
            pipe.prefetch(2, d_xT + ((size_t)(t + 1) * 128) * 128, tid == 0);
            pipe.prefetch(0, d_xT + ((size_t)(t + 1) * 128 + 64) * 128, tid == 0);
        }
        const int b = bidx;
        if (tid < OCOLS) so[tid] = d_o194[(size_t)b * OPAD + tid];
        __syncthreads();

        if (tid < STKD) Vs[t * STKD + tid] = so[tid];
        float u_ = sigf(so[192]);
        float dd = sigf(so[193]);

        // sp/sA using PRECOMPUTED ssuf/csum (from previous I3 / init)
        for (int i = tid; i < MAXT; i += NTHR) {
            float si   = ss[i];
            float prod = ssuf[i] + csum[i >> 5] - si;
            float sp   = fmaxf(0.0f, si - fmaxf(0.0f, u_ - prod));
            if (i == t) sp = dd;
            float inner = fmaxf(0.0f, 1.0f - prod - sp);
            sA[i] = fminf(sp, inner);
            if (i <= t) ss[i] = sp;
        }
        __syncthreads();

        // r_t[d] = sum_{i<=t} A[i] * V[i][d]   (all smem, 4-way MLP)
        {
            const int dcol = tid & 63, q = tid >> 6;   // q 0..3, stride 4
            float a0 = 0.f, a1 = 0.f, a2 = 0.f, a3 = 0.f;
            int i = q;
            for (; i + 12 <= t; i += 16) {
                a0 = fmaf(sA[i],      Vs[i * 64 + dcol],        a0);
                a1 = fmaf(sA[i + 4],  Vs[(i + 4) * 64 + dcol],  a1);
                a2 = fmaf(sA[i + 8],  Vs[(i + 8) * 64 + dcol],  a2);
                a3 = fmaf(sA[i + 12], Vs[(i + 12) * 64 + dcol], a3);
            }
            for (; i <= t; i += 4)
                a0 = fmaf(sA[i], Vs[i * 64 + dcol], a0);
            sred[q * 64 + dcol] = (a0 + a1) + (a2 + a3);
        }
        __syncthreads();
        if (tid < STKD)
            d_RH[(size_t)tid * 128 + b] =
                sred[tid] + sred[64 + tid] + sred[128 + tid] + sred[192 + tid];

        if (t == NSTEPS - 1) {
            __syncthreads();
            SOFTMAX_OUT(t)           // last step's output (no I3 follows)
            grid_sync(n);
            break;
        }

        // x-chunk-0 GEMM (slot2) BEFORE the barrier: static data, hides
        // compute in barrier-arrival skew.
        if (has_x) {
            pipe.wait(2);
            GEMM_CHUNK(As + 2 * CHF, 0)
            __syncthreads();
        }
        grid_sync(n);

        // ---------- I3: softmax + next-step scan + x1 + r chunk + cell ------
        {
            const int rslot = has_x ? 1 : 2;      // slot consumed last in I1
            pipe.prefetch(rslot, d_RH, tid == 0); // r chunk
            if (t >= KSTART) { SOFTMAX_OUT(t) }   // overlaps r TMA
            SCAN_SS()                             // suffix scan for step t+1
            if (has_x) {
                pipe.wait(0);                     // x chunk 1 (slot0)
                GEMM_CHUNK(As, 64)
            }
            pipe.wait(rslot);                     // r chunk
            GEMM_CHUNK(As + rslot * CHF, 128)
        }
        EPILOGUE_CELL()
        grid_sync(n);
    }
}

extern "C" void kernel_launch(void *const *d_in, const int *in_sizes, int n_in,
                              void *d_out, int out_size) {
    (void)in_sizes; (void)n_in; (void)out_size;
    const float *x   = (const float *)d_in[0];
    const float *Wih = (const float *)d_in[1];
    const float *bih = (const float *)d_in[2];
    const float *Whh = (const float *)d_in[3];
    const float *bhh = (const float *)d_in[4];
    const float *Wr  = (const float *)d_in[5];
    const float *br  = (const float *)d_in[6];
    float *out = (float *)d_out;

    cudaFuncSetAttribute(lstm_stack_kernel,
                         cudaFuncAttributeMaxDynamicSharedMemorySize, SMEMB);

    void *p;
    cudaGetSymbolAddress(&p, d_RH);  cudaMemsetAsync(p, 0, sizeof(float) * (64 + 512) * 128);
    cudaGetSymbolAddress(&p, g_bar); cudaMemsetAsync(p, 0, sizeof(unsigned));

    lstm_stack_kernel<<<GRIDN, NTHR, SMEMB>>>(x, Wih, bih, Whh, bhh, Wr, br, out);
}

// round 16
// speedup vs baseline: 1.0916x; 1.0916x over previous
#include <cuda_runtime.h>
#include <math.h>
#include <stdint.h>

// ---------------------------------------------------------------------------
// LSTM + differentiable stack, 259 steps, persistent kernel, 128 CTAs x 256 thr.
// GEMM tile (proven R12): 4 cols x 8 batches x 4-way k-split FFMA2 at pipe floor.
// R15 = R13 (best, 4482us) + parallel epilogue k-reduce (all 256 threads,
// conflict-free stride-18 smem layout, identical summation order) + removal of
// redundant __syncthreads (subsumed by following barriers).
//  I1: gates h-part (8 x 64k chunks, double-buffered TMA) + fused f32x2 readout.
//  I2: CTA b: V store, sp/sA (scan precomputed in prior I3), gather -> r_t.
//      x_{t+1} TMAs issued at I2 start; x0 GEMM pre-barrier.
//  I3: softmax + next-step scan (overlap r TMA) + x1 + r + k-reduce + cell.
// Grid barrier: red.release.gpu + ld.acquire poll.
// ---------------------------------------------------------------------------

#define BATCH   128
#define HID     512
#define INPD    128
#define STKD    64
#define MAXT    259
#define NSTEPS  259
#define KSTART  129
#define OCOLS   194
#define OPAD    208

#define GRIDN   128
#define NTHR    256
#define KCH     64
#define CHF     (KCH * BATCH)            // 8192 floats per chunk
#define CHB     (CHF * 4)                // 32768 B per chunk
#define RSTRIDE 18                       // u64 row stride for k-reduce scratch

// smem float offsets (R13 layout)
#define OFF_WS   0                       // 704 x 16 scalar W (11264 f)
#define OFF_AS   11264                   // 2 x (64 x 128) A chunk buffers (16384 f)
#define OFF_V    27648                   // 259 x 64 stack V (16576 f)
#define OFF_WRD  44224                   // 1024 u64 dup Wr (2048 f)
#define OFF_GS   46272                   // 16 x 132 gate exchange (2112 f)
#define OFF_SC   48384                   // 512 c-state
#define OFF_SB   48896                   // 16 gate bias
#define OFF_SBR  48912                   // 2 readout bias
#define OFF_SS   48914                   // 292 stack s
#define OFF_MB   49208                   // 2 mbarriers (16 B, 8-aligned)
#define OFF_SO   49212                   // 208 o194 row
#define OFF_SUF  49420                   // 288 suffix
#define OFF_SA   49708                   // 288 A coeffs
#define OFF_CS   49996                   // 32
#define OFF_SRD  50028                   // 256 gather reduce
#define OFF_SRR  50284                   // 1024 readout reduce
#define SMEMF    51308
#define SMEMB    (SMEMF * 4)             // 205232 B

__device__ float d_xT[129 * 128 * 128];      // x transposed [t][k][b]
__device__ float d_RH[(64 + 512) * 128];     // rows 0..63: r ; 64..575: h  ([k][b])
__device__ float d_o194[BATCH * OPAD];       // readout batch-major [b][n]
__device__ unsigned g_bar;

__device__ __forceinline__ float sigf(float x) { return 1.0f / (1.0f + expf(-x)); }

#define FFMA2(acc, a, w) \
    asm volatile("fma.rn.f32x2 %0, %1, %2, %0;" : "+l"(acc) : "l"(a), "l"(w))
#define ADDF2(acc, a) \
    asm volatile("add.rn.f32x2 %0, %0, %1;" : "+l"(acc) : "l"(a))
#define DUP2(d, s) \
    asm volatile("mov.b64 %0, {%1, %1};" : "=l"(d) : "r"(__float_as_uint(s)))

// Grid barrier: release-REDG arrival + acquire-load poll.
__device__ __forceinline__ void grid_sync(unsigned &n) {
    __syncthreads();
    n += (unsigned)GRIDN;
    if (threadIdx.x == 0) {
        asm volatile("red.release.gpu.global.add.u32 [%0], %1;"
                     :: "l"(&g_bar), "r"(1u) : "memory");
        unsigned v;
        do {
            asm volatile("ld.acquire.gpu.global.u32 %0, [%1];"
                         : "=r"(v) : "l"(&g_bar));
        } while ((int)(v - n) < 0);
    }
    __syncthreads();
}

__device__ __forceinline__ void mbar_init(uint32_t mbar) {
    asm volatile("mbarrier.init.shared.b64 [%0], %1;" :: "r"(mbar), "r"(1u) : "memory");
}
__device__ __forceinline__ void mbar_expect(uint32_t mbar, uint32_t bytes) {
    asm volatile("mbarrier.arrive.expect_tx.shared.b64 _, [%0], %1;"
                 :: "r"(mbar), "r"(bytes) : "memory");
}
__device__ __forceinline__ void bulk_ld(uint32_t dst, const float *src,
                                        uint32_t bytes, uint32_t mbar) {
    asm volatile("cp.async.bulk.shared::cluster.global.mbarrier::complete_tx::bytes "
                 "[%0], [%1], %2, [%3];"
                 :: "r"(dst), "l"(src), "r"(bytes), "r"(mbar) : "memory");
}
__device__ __forceinline__ void mbar_wait(uint32_t mbar, uint32_t parity) {
    asm volatile(
        "{\n\t.reg .pred P;\n\t"
        "WL_%=:\n\t"
        "mbarrier.try_wait.parity.acquire.cta.shared::cta.b64 P, [%0], %1, 0x989680;\n\t"
        "@P bra.uni WD_%=;\n\t"
        "bra.uni WL_%=;\n\t"
        "WD_%=:\n\t}"
        :: "r"(mbar), "r"(parity) : "memory");
}

struct Pipe {
    uint32_t mb0, mb1, as0, as1;
    unsigned ph;
    __device__ __forceinline__ void prefetch(int buf, const float *src, bool issuer) {
        if (issuer) {
            uint32_t mb = buf ? mb1 : mb0;
            mbar_expect(mb, CHB);
            bulk_ld(buf ? as1 : as0, src, CHB, mb);
        }
    }
    __device__ __forceinline__ void wait(int buf) {
        mbar_wait(buf ? mb1 : mb0, (ph >> buf) & 1u);
        ph ^= (1u << buf);
    }
};

__global__ void __launch_bounds__(NTHR, 1)
lstm_stack_kernel(const float *__restrict__ x,
                  const float *__restrict__ Wih, const float *__restrict__ bih,
                  const float *__restrict__ Whh, const float *__restrict__ bhh,
                  const float *__restrict__ Wr, const float *__restrict__ br,
                  float *__restrict__ out) {
    extern __shared__ __align__(16) float smf[];
    float *Ws   = smf + OFF_WS;
    float *As   = smf + OFF_AS;
    float *Vs   = smf + OFF_V;
    unsigned long long *Wrd = (unsigned long long *)(smf + OFF_WRD);
    float *gs   = smf + OFF_GS;
    float *sc   = smf + OFF_SC;
    float *sb   = smf + OFF_SB;
    float *sbr  = smf + OFF_SBR;
    float *ss   = smf + OFF_SS;
    float *so   = smf + OFF_SO;
    float *ssuf = smf + OFF_SUF;
    float *sA   = smf + OFF_SA;
    float *csum = smf + OFF_CS;
    float *sred = smf + OFF_SRD;
    float *srr  = smf + OFF_SRR;

    const int tid  = threadIdx.x;
    const int bidx = blockIdx.x;
    const int lane = tid & 31, wid = tid >> 5;
    unsigned n = 0;

    Pipe pipe;
    pipe.mb0 = (uint32_t)__cvta_generic_to_shared(smf + OFF_MB);
    pipe.mb1 = pipe.mb0 + 8;
    pipe.as0 = (uint32_t)__cvta_generic_to_shared(As);
    pipe.as1 = pipe.as0 + CHB;
    pipe.ph  = 0;
    if (tid == 0) { mbar_init(pipe.mb0); mbar_init(pipe.mb1); }
    __syncthreads();

    // ---------------- prologue: transpose x[t] -> d_xT[t][k][b] -------------
    {
        float *tile = smf;  // 128x132 scratch inside Ws+As region (loaded later)
        for (int p = bidx; p < KSTART; p += GRIDN) {
#pragma unroll
            for (int q = 0; q < 16; ++q) {
                int idx = q * 1024 + tid * 4;
                int b = idx >> 7, k = idx & 127;
                float4 v = *(const float4 *)(x + ((size_t)p * 128 + b) * 128 + k);
                tile[b * 132 + k]     = v.x;
                tile[b * 132 + k + 1] = v.y;
                tile[b * 132 + k + 2] = v.z;
                tile[b * 132 + k + 3] = v.w;
            }
            __syncthreads();
#pragma unroll
            for (int q = 0; q < 16; ++q) {
                int idx = q * 1024 + tid * 4;
                int k = idx >> 7, b = idx & 127;
                float4 v = make_float4(tile[b * 132 + k], tile[(b + 1) * 132 + k],
                                       tile[(b + 2) * 132 + k], tile[(b + 3) * 132 + k]);
                *(float4 *)(d_xT + ((size_t)p * 128 + k) * 128 + b) = v;
            }
            __syncthreads();
        }
    }
    grid_sync(n);

    // ---------------- persistent loads ----------------
    for (int idx = tid; idx < 704 * 16; idx += NTHR) {
        int k = idx >> 4, cidx = idx & 15;
        int m = cidx >> 2, u = cidx & 3;
        int grow = m * 512 + bidx * 4 + u;
        Ws[idx] = (k < 192) ? Wih[(size_t)grow * 192 + k]
                            : Whh[(size_t)grow * 512 + (k - 192)];
    }
    for (int idx = tid; idx < 1024; idx += NTHR) {
        int c = idx >> 9, k = idx & 511;
        int nn = bidx + c * 128;
        float w = (nn < OCOLS) ? Wr[(size_t)nn * HID + k] : 0.0f;
        unsigned ub = __float_as_uint(w);
        Wrd[c * 512 + k] = (unsigned long long)ub | ((unsigned long long)ub << 32);
    }
    if (tid < 16) {
        int m = tid >> 2, u = tid & 3;
        int grow = m * 512 + bidx * 4 + u;
        sb[tid] = bih[grow] + bhh[grow];
    }
    if (tid < 2) {
        int nn = bidx + tid * 128;
        sbr[tid] = (nn < OCOLS) ? br[nn] : 0.0f;
    }
    for (int idx = tid; idx < 512; idx += NTHR) sc[idx] = 0.0f;
    for (int idx = tid; idx < 292; idx += NTHR) ss[idx] = 0.0f;
    for (int idx = tid; idx < 288; idx += NTHR) ssuf[idx] = 0.0f;  // scan of zeros
    if (tid < 32) csum[tid] = 0.0f;
    for (int idx = tid; idx < MAXT * STKD; idx += NTHR) Vs[idx] = 0.0f;
    __syncthreads();

    // GEMM thread mapping: 4 cols x 8 batches x 4-way k-split
    const int tx = tid & 3;            // col quad (cols 4tx..4tx+3)
    const int bo = (tid >> 2) & 15;    // batch octet (batches bo*8..bo*8+7)
    const int kq = tid >> 6;           // k-quarter within each 64-k chunk
    // readout mapping
    const int rc  = tid >> 7;            // col 0/1
    const int rks = (tid >> 5) & 3;      // k-split (16 kk each)
    const int rbq = tid & 31;            // batch quad

    unsigned long long acc0, acc1, acc2, acc3, acc4, acc5, acc6, acc7,
                       acc8, acc9, acc10, acc11, acc12, acc13, acc14, acc15;

#define ZERO_ACCS() \
    acc0 = acc1 = acc2 = acc3 = acc4 = acc5 = acc6 = acc7 = 0ull;   \
    acc8 = acc9 = acc10 = acc11 = acc12 = acc13 = acc14 = acc15 = 0ull;

// GEMM over one resident 64-k chunk: this thread covers its 16-k quarter.
#define GEMM_CHUNK(Ab, wrow)                                                  \
    {                                                                         \
        const float *Ab_ = (Ab) + kq * 16 * 128 + bo * 8;                     \
        const float *wp_ = Ws + (size_t)((wrow) + kq * 16) * 16 + tx * 4;     \
        _Pragma("unroll")                                                     \
        for (int kk = 0; kk < 16; ++kk) {                                     \
            ulonglong2 a01 = *(const ulonglong2 *)(Ab_ + kk * 128);           \
            ulonglong2 a23 = *(const ulonglong2 *)(Ab_ + kk * 128 + 4);       \
            float4 w = *(const float4 *)(wp_ + kk * 16);                      \
            unsigned long long w0, w1, w2, w3;                                \
            DUP2(w0, w.x); DUP2(w1, w.y); DUP2(w2, w.z); DUP2(w3, w.w);       \
            FFMA2(acc0,  a01.x, w0); FFMA2(acc1,  a01.y, w0);                 \
            FFMA2(acc2,  a23.x, w0); FFMA2(acc3,  a23.y, w0);                 \
            FFMA2(acc4,  a01.x, w1); FFMA2(acc5,  a01.y, w1);                 \
            FFMA2(acc6,  a23.x, w1); FFMA2(acc7,  a23.y, w1);                 \
            FFMA2(acc8,  a01.x, w2); FFMA2(acc9,  a01.y, w2);                 \
            FFMA2(acc10, a23.x, w2); FFMA2(acc11, a23.y, w2);                 \
            FFMA2(acc12, a01.x, w3); FFMA2(acc13, a01.y, w3);                 \
            FFMA2(acc14, a23.x, w3); FFMA2(acc15, a23.y, w3);                 \
        }                                                                     \
    }

// Parallel 4-way k-split reduce: ALL threads dump accs to stride-18 smem rows
// (conflict-free), then each thread reduces 4 u64 (8 outputs, same sum order
// as before: kq0 + kq1 + kq2 + kq3) and writes gs + bias. Then LSTM cell.
#define EPILOGUE_CELL()                                                       \
    __syncthreads();                                                          \
    {                                                                         \
        unsigned long long *red_ = (unsigned long long *)As;                  \
        unsigned long long *d_ = red_ + (size_t)(kq * 64 + (tid & 63)) * RSTRIDE; \
        *(ulonglong2 *)(d_)      = make_ulonglong2(acc0,  acc1);              \
        *(ulonglong2 *)(d_ + 2)  = make_ulonglong2(acc2,  acc3);              \
        *(ulonglong2 *)(d_ + 4)  = make_ulonglong2(acc4,  acc5);              \
        *(ulonglong2 *)(d_ + 6)  = make_ulonglong2(acc6,  acc7);              \
        *(ulonglong2 *)(d_ + 8)  = make_ulonglong2(acc8,  acc9);              \
        *(ulonglong2 *)(d_ + 10) = make_ulonglong2(acc10, acc11);             \
        *(ulonglong2 *)(d_ + 12) = make_ulonglong2(acc12, acc13);             \
        *(ulonglong2 *)(d_ + 14) = make_ulonglong2(acc14, acc15);             \
        __syncthreads();                                                      \
        {                                                                     \
            const int pos2 = tid >> 2;                                        \
            const int i0   = (tid & 3) * 4;                                   \
            const unsigned long long *r0_ = red_ + (size_t)pos2 * RSTRIDE + i0;            \
            const unsigned long long *r1_ = red_ + (size_t)(64 + pos2) * RSTRIDE + i0;     \
            const unsigned long long *r2_ = red_ + (size_t)(128 + pos2) * RSTRIDE + i0;    \
            const unsigned long long *r3_ = red_ + (size_t)(192 + pos2) * RSTRIDE + i0;    \
            ulonglong2 pA = *(const ulonglong2 *)(r0_);                       \
            ulonglong2 pB = *(const ulonglong2 *)(r0_ + 2);                   \
            ulonglong2 qA = *(const ulonglong2 *)(r1_);                       \
            ulonglong2 qB = *(const ulonglong2 *)(r1_ + 2);                   \
            ADDF2(pA.x, qA.x); ADDF2(pA.y, qA.y);                             \
            ADDF2(pB.x, qB.x); ADDF2(pB.y, qB.y);                             \
            qA = *(const ulonglong2 *)(r2_);                                  \
            qB = *(const ulonglong2 *)(r2_ + 2);                              \
            ADDF2(pA.x, qA.x); ADDF2(pA.y, qA.y);                             \
            ADDF2(pB.x, qB.x); ADDF2(pB.y, qB.y);                             \
            qA = *(const ulonglong2 *)(r3_);                                  \
            qB = *(const ulonglong2 *)(r3_ + 2);                              \
            ADDF2(pA.x, qA.x); ADDF2(pA.y, qA.y);                             \
            ADDF2(pB.x, qB.x); ADDF2(pB.y, qB.y);                             \
            const int col_ = ((tid >> 2) & 3) * 4 + (tid & 3);                \
            const int bo_  = tid >> 4;                                        \
            float bs_ = sb[col_];                                             \
            float *gp_ = gs + col_ * 132 + bo_ * 8;                           \
            *(float4 *)gp_ = make_float4(                                     \
                __uint_as_float((unsigned)pA.x) + bs_,                        \
                __uint_as_float((unsigned)(pA.x >> 32)) + bs_,                \
                __uint_as_float((unsigned)pA.y) + bs_,                        \
                __uint_as_float((unsigned)(pA.y >> 32)) + bs_);               \
            *(float4 *)(gp_ + 4) = make_float4(                               \
                __uint_as_float((unsigned)pB.x) + bs_,                        \
                __uint_as_float((unsigned)(pB.x >> 32)) + bs_,                \
                __uint_as_float((unsigned)pB.y) + bs_,                        \
                __uint_as_float((unsigned)(pB.y >> 32)) + bs_);               \
        }                                                                     \
    }                                                                         \
    __syncthreads();                                                          \
    _Pragma("unroll")                                                         \
    for (int r = 0; r < 2; ++r) {                                             \
        int idx = tid + r * NTHR;                                             \
        int u = idx >> 7, bb = idx & 127;                                     \
        float gi = gs[u * 132 + bb];                                          \
        float gf = gs[(4 + u) * 132 + bb];                                    \
        float gg = gs[(8 + u) * 132 + bb];                                    \
        float go = gs[(12 + u) * 132 + bb];                                   \
        float c2 = sigf(gf) * sc[idx] + sigf(gi) * tanhf(gg);                 \
        sc[idx] = c2;                                                         \
        d_RH[(size_t)(64 + bidx * 4 + u) * 128 + bb] = sigf(go) * tanhf(c2);  \
    }

// Suffix scan of ss -> ssuf, csum (for the NEXT step's I2).
#define SCAN_SS()                                                             \
    for (int cch = wid; cch < 9; cch += 8) {                                  \
        float v = ss[cch * 32 + lane];                                        \
        _Pragma("unroll")                                                     \
        for (int o = 1; o < 32; o <<= 1) {                                    \
            float tv = __shfl_down_sync(0xffffffffu, v, o);                   \
            if (lane + o < 32) v += tv;                                       \
        }                                                                     \
        ssuf[cch * 32 + lane] = v;                                            \
        if (lane == 0) csum[cch] = v;                                         \
    }                                                                         \
    __syncthreads();                                                          \
    if (wid == 0) {                                                           \
        float tv = (lane < 9) ? csum[lane] : 0.0f;                            \
        float vv = tv;                                                        \
        _Pragma("unroll")                                                     \
        for (int o = 1; o < 16; o <<= 1) {                                    \
            float sh = __shfl_down_sync(0xffffffffu, vv, o);                  \
            if (lane + o < 16) vv += sh;                                      \
        }                                                                     \
        if (lane < 9) csum[lane] = vv - tv;                                   \
    }

// Log-softmax of so[64..191] -> out row (t >= KSTART). Uses csum as scratch;
// must run BEFORE SCAN_SS() in the same phase.
#define SOFTMAX_OUT(tt)                                                       \
    {                                                                         \
        float v = (tid < INPD) ? so[STKD + tid] : -1e30f;                     \
        float m = v;                                                          \
        _Pragma("unroll")                                                     \
        for (int o = 16; o; o >>= 1)                                          \
            m = fmaxf(m, __shfl_xor_sync(0xffffffffu, m, o));                 \
        if (lane == 0) csum[wid] = m;                                         \
        __syncthreads();                                                      \
        float mm = csum[0];                                                   \
        _Pragma("unroll")                                                     \
        for (int w = 1; w < 8; ++w) mm = fmaxf(mm, csum[w]);                  \
        float e = (tid < INPD) ? expf(v - mm) : 0.0f;                         \
        _Pragma("unroll")                                                     \
        for (int o = 16; o; o >>= 1)                                          \
            e += __shfl_xor_sync(0xffffffffu, e, o);                          \
        if (lane == 0) csum[8 + wid] = e;                                     \
        __syncthreads();                                                      \
        float tot = 0.0f;                                                     \
        _Pragma("unroll")                                                     \
        for (int w = 0; w < 8; ++w) tot += csum[8 + w];                       \
        float ls = logf(tot);                                                 \
        if (tid < INPD)                                                       \
            out[(((size_t)((tt) - KSTART)) * BATCH + bidx) * INPD + tid] =    \
                v - mm - ls;                                                  \
        __syncthreads();                                                      \
    }

    // ================= init: gates_0 = x_0 part only; cell -> h_0 ===========
    ZERO_ACCS()
    pipe.prefetch(0, d_xT, tid == 0);
    pipe.prefetch(1, d_xT + 64 * 128, tid == 0);
    pipe.wait(0);
    GEMM_CHUNK(As, 0)
    pipe.wait(1);
    GEMM_CHUNK(As + CHF, 64)
    EPILOGUE_CELL()
    grid_sync(n);

    // =========================== main time loop =============================
    for (int t = 0; t < NSTEPS; ++t) {
        const bool has_x = (t < 128);

        // ---------- I1: h gate chunks + fused readout ----------
        pipe.prefetch(0, d_RH + (size_t)64 * 128, tid == 0);  // h chunk 0, asap
        ZERO_ACCS()
        unsigned long long racc0 = 0ull, racc1 = 0ull;
#pragma unroll 1
        for (int ci = 0; ci < 8; ++ci) {
            if (ci + 1 < 8)
                pipe.prefetch((ci + 1) & 1,
                              d_RH + (size_t)(64 + (ci + 1) * 64) * 128, tid == 0);
            pipe.wait(ci & 1);
            const float *Ab = As + (ci & 1) * CHF;
            GEMM_CHUNK(Ab, 192 + ci * 64)
            {   // f32x2 readout over this h chunk
                const float *Ar = Ab + (rks * 16) * 128 + rbq * 4;
                const unsigned long long *wr = Wrd + rc * 512 + ci * 64 + rks * 16;
#pragma unroll
                for (int m = 0; m < 16; ++m) {
                    ulonglong2 a = *(const ulonglong2 *)(Ar + m * 128);
                    unsigned long long w = wr[m];
                    FFMA2(racc0, a.x, w);
                    FFMA2(racc1, a.y, w);
                }
            }
            if (ci < 7) __syncthreads();   // last-chunk sync subsumed below
        }
        // readout reduce + store o194 batch-major
        {
            float4 rv = make_float4(__uint_as_float((unsigned)racc0),
                                    __uint_as_float((unsigned)(racc0 >> 32)),
                                    __uint_as_float((unsigned)racc1),
                                    __uint_as_float((unsigned)(racc1 >> 32)));
            *(float4 *)(srr + rks * 256 + rc * 128 + rbq * 4) = rv;
        }
        __syncthreads();
        {
            int c = tid >> 7, b = tid & 127;
            int nn = bidx + c * 128;
            if (nn < OCOLS) {
                float o = srr[b + c * 128] + srr[256 + b + c * 128] +
                          srr[512 + b + c * 128] + srr[768 + b + c * 128] + sbr[c];
                d_o194[(size_t)b * OPAD + nn] = o;
            }
        }
        grid_sync(n);

        // ---------- I2: stack update for batch b = bidx (SHORT chain) -------
        // x_{t+1} chunk TMAs issued now: buffers idle during I2, d_xT static.
        if (has_x) {
            pipe.prefetch(0, d_xT + ((size_t)(t + 1) * 128) * 128, tid == 0);
            pipe.prefetch(1, d_xT + ((size_t)(t + 1) * 128 + 64) * 128, tid == 0);
        }
        const int b = bidx;
        if (tid < OCOLS) so[tid] = d_o194[(size_t)b * OPAD + tid];
        __syncthreads();

        if (tid < STKD) Vs[t * STKD + tid] = so[tid];
        float u_ = sigf(so[192]);
        float dd = sigf(so[193]);

        // sp/sA using PRECOMPUTED ssuf/csum (from previous I3 / init)
        for (int i = tid; i < MAXT; i += NTHR) {
            float si   = ss[i];
            float prod = ssuf[i] + csum[i >> 5] - si;
            float sp   = fmaxf(0.0f, si - fmaxf(0.0f, u_ - prod));
            if (i == t) sp = dd;
            float inner = fmaxf(0.0f, 1.0f - prod - sp);
            sA[i] = fminf(sp, inner);
            if (i <= t) ss[i] = sp;
        }
        __syncthreads();

        // r_t[d] = sum_{i<=t} A[i] * V[i][d]   (all smem, 4-way MLP)
        {
            const int dcol = tid & 63, q = tid >> 6;   // q 0..3, stride 4
            float a0 = 0.f, a1 = 0.f, a2 = 0.f, a3 = 0.f;
            int i = q;
            for (; i + 12 <= t; i += 16) {
                a0 = fmaf(sA[i],      Vs[i * 64 + dcol],        a0);
                a1 = fmaf(sA[i + 4],  Vs[(i + 4) * 64 + dcol],  a1);
                a2 = fmaf(sA[i + 8],  Vs[(i + 8) * 64 + dcol],  a2);
                a3 = fmaf(sA[i + 12], Vs[(i + 12) * 64 + dcol], a3);
            }
            for (; i <= t; i += 4)
                a0 = fmaf(sA[i], Vs[i * 64 + dcol], a0);
            sred[q * 64 + dcol] = (a0 + a1) + (a2 + a3);
        }
        __syncthreads();
        if (tid < STKD)
            d_RH[(size_t)tid * 128 + b] =
                sred[tid] + sred[64 + tid] + sred[128 + tid] + sred[192 + tid];

        if (t == NSTEPS - 1) {
            __syncthreads();
            SOFTMAX_OUT(t)           // last step's output (no I3 follows)
            grid_sync(n);
            break;
        }

        // x-chunk-0 GEMM BEFORE the barrier: depends only on static d_xT,
        // hides its compute in barrier-arrival skew. (buffer-safety sync is
        // subsumed by grid_sync's leading __syncthreads.)
        if (has_x) {
            pipe.wait(0);
            GEMM_CHUNK(As, 0)
        }
        grid_sync(n);

        // ---------- I3: softmax + next-step scan + x1 + r chunk + cell ------
        pipe.prefetch(0, d_RH, tid == 0);       // r chunk into buf0
        if (t >= KSTART) { SOFTMAX_OUT(t) }     // overlaps r TMA (no x here)
        SCAN_SS()                               // suffix scan for step t+1
        if (has_x) {
            pipe.wait(1);                       // x chunk 1 (issued in I2)
            GEMM_CHUNK(As + CHF, 64)
        }
        pipe.wait(0);                           // r chunk
        GEMM_CHUNK(As, 128)
        EPILOGUE_CELL()
        grid_sync(n);
    }
}

extern "C" void kernel_launch(void *const *d_in, const int *in_sizes, int n_in,
                              void *d_out, int out_size) {
    (void)in_sizes; (void)n_in; (void)out_size;
    const float *x   = (const float *)d_in[0];
    const float *Wih = (const float *)d_in[1];
    const float *bih = (const float *)d_in[2];
    const float *Whh = (const float *)d_in[3];
    const float *bhh = (const float *)d_in[4];
    const float *Wr  = (const float *)d_in[5];
    const float *br  = (const float *)d_in[6];
    float *out = (float *)d_out;

    cudaFuncSetAttribute(lstm_stack_kernel,
                         cudaFuncAttributeMaxDynamicSharedMemorySize, SMEMB);

    void *p;
    cudaGetSymbolAddress(&p, d_RH);  cudaMemsetAsync(p, 0, sizeof(float) * (64 + 512) * 128);
    cudaGetSymbolAddress(&p, g_bar); cudaMemsetAsync(p, 0, sizeof(unsigned));

    lstm_stack_kernel<<<GRIDN, NTHR, SMEMB>>>(x, Wih, bih, Whh, bhh, Wr, br, out);
}

// round 17
// speedup vs baseline: 1.1123x; 1.0190x over previous
#include <cuda_runtime.h>
#include <math.h>
#include <stdint.h>

// ---------------------------------------------------------------------------
// LSTM + differentiable stack, 259 steps, persistent kernel, 128 CTAs x 256 thr.
// GEMM tile (proven R12): 4 cols x 8 batches x 4-way k-split FFMA2 at pipe floor.
// R16 = R15 (best, 4169us) + two serial-window overlaps:
//   - I2 (t<128): o194-row LDG issued first, hidden under x0 TMA-wait + GEMM
//     (pre-barrier x0 slot removed).
//   - I3 (t>=129): softmax (warps 0-3, scratch sred, named bar 1) runs
//     CONCURRENTLY with the suffix scan (warps 4-7, named bar 2).
//  I1: gates h-part (8 x 64k chunks, double-buffered TMA) + fused f32x2 readout.
//  I2: x TMAs + so-LDG; x0 GEMM under LDG; V store, sp/sA, gather -> r_t.
//  I3: softmax||scan + x1 + r + parallel k-reduce + cell.
// Grid barrier: red.release.gpu + ld.acquire poll.
// ---------------------------------------------------------------------------

#define BATCH   128
#define HID     512
#define INPD    128
#define STKD    64
#define MAXT    259
#define NSTEPS  259
#define KSTART  129
#define OCOLS   194
#define OPAD    208

#define GRIDN   128
#define NTHR    256
#define KCH     64
#define CHF     (KCH * BATCH)            // 8192 floats per chunk
#define CHB     (CHF * 4)                // 32768 B per chunk
#define RSTRIDE 18                       // u64 row stride for k-reduce scratch

// smem float offsets (R13/R15 layout)
#define OFF_WS   0                       // 704 x 16 scalar W (11264 f)
#define OFF_AS   11264                   // 2 x (64 x 128) A chunk buffers (16384 f)
#define OFF_V    27648                   // 259 x 64 stack V (16576 f)
#define OFF_WRD  44224                   // 1024 u64 dup Wr (2048 f)
#define OFF_GS   46272                   // 16 x 132 gate exchange (2112 f)
#define OFF_SC   48384                   // 512 c-state
#define OFF_SB   48896                   // 16 gate bias
#define OFF_SBR  48912                   // 2 readout bias
#define OFF_SS   48914                   // 292 stack s
#define OFF_MB   49208                   // 2 mbarriers (16 B, 8-aligned)
#define OFF_SO   49212                   // 208 o194 row
#define OFF_SUF  49420                   // 288 suffix
#define OFF_SA   49708                   // 288 A coeffs
#define OFF_CS   49996                   // 32
#define OFF_SRD  50028                   // 256 gather reduce / I3 softmax scratch
#define OFF_SRR  50284                   // 1024 readout reduce
#define SMEMF    51308
#define SMEMB    (SMEMF * 4)             // 205232 B

__device__ float d_xT[129 * 128 * 128];      // x transposed [t][k][b]
__device__ float d_RH[(64 + 512) * 128];     // rows 0..63: r ; 64..575: h  ([k][b])
__device__ float d_o194[BATCH * OPAD];       // readout batch-major [b][n]
__device__ unsigned g_bar;

__device__ __forceinline__ float sigf(float x) { return 1.0f / (1.0f + expf(-x)); }

#define FFMA2(acc, a, w) \
    asm volatile("fma.rn.f32x2 %0, %1, %2, %0;" : "+l"(acc) : "l"(a), "l"(w))
#define ADDF2(acc, a) \
    asm volatile("add.rn.f32x2 %0, %0, %1;" : "+l"(acc) : "l"(a))
#define DUP2(d, s) \
    asm volatile("mov.b64 %0, {%1, %1};" : "=l"(d) : "r"(__float_as_uint(s)))
#define BARN(id, cnt) \
    asm volatile("bar.sync %0, %1;" :: "r"(id), "r"(cnt) : "memory")

// Grid barrier: release-REDG arrival + acquire-load poll.
__device__ __forceinline__ void grid_sync(unsigned &n) {
    __syncthreads();
    n += (unsigned)GRIDN;
    if (threadIdx.x == 0) {
        asm volatile("red.release.gpu.global.add.u32 [%0], %1;"
                     :: "l"(&g_bar), "r"(1u) : "memory");
        unsigned v;
        do {
            asm volatile("ld.acquire.gpu.global.u32 %0, [%1];"
                         : "=r"(v) : "l"(&g_bar));
        } while ((int)(v - n) < 0);
    }
    __syncthreads();
}

__device__ __forceinline__ void mbar_init(uint32_t mbar) {
    asm volatile("mbarrier.init.shared.b64 [%0], %1;" :: "r"(mbar), "r"(1u) : "memory");
}
__device__ __forceinline__ void mbar_expect(uint32_t mbar, uint32_t bytes) {
    asm volatile("mbarrier.arrive.expect_tx.shared.b64 _, [%0], %1;"
                 :: "r"(mbar), "r"(bytes) : "memory");
}
__device__ __forceinline__ void bulk_ld(uint32_t dst, const float *src,
                                        uint32_t bytes, uint32_t mbar) {
    asm volatile("cp.async.bulk.shared::cluster.global.mbarrier::complete_tx::bytes "
                 "[%0], [%1], %2, [%3];"
                 :: "r"(dst), "l"(src), "r"(bytes), "r"(mbar) : "memory");
}
__device__ __forceinline__ void mbar_wait(uint32_t mbar, uint32_t parity) {
    asm volatile(
        "{\n\t.reg .pred P;\n\t"
        "WL_%=:\n\t"
        "mbarrier.try_wait.parity.acquire.cta.shared::cta.b64 P, [%0], %1, 0x989680;\n\t"
        "@P bra.uni WD_%=;\n\t"
        "bra.uni WL_%=;\n\t"
        "WD_%=:\n\t}"
        :: "r"(mbar), "r"(parity) : "memory");
}

struct Pipe {
    uint32_t mb0, mb1, as0, as1;
    unsigned ph;
    __device__ __forceinline__ void prefetch(int buf, const float *src, bool issuer) {
        if (issuer) {
            uint32_t mb = buf ? mb1 : mb0;
            mbar_expect(mb, CHB);
            bulk_ld(buf ? as1 : as0, src, CHB, mb);
        }
    }
    __device__ __forceinline__ void wait(int buf) {
        mbar_wait(buf ? mb1 : mb0, (ph >> buf) & 1u);
        ph ^= (1u << buf);
    }
};

__global__ void __launch_bounds__(NTHR, 1)
lstm_stack_kernel(const float *__restrict__ x,
                  const float *__restrict__ Wih, const float *__restrict__ bih,
                  const float *__restrict__ Whh, const float *__restrict__ bhh,
                  const float *__restrict__ Wr, const float *__restrict__ br,
                  float *__restrict__ out) {
    extern __shared__ __align__(16) float smf[];
    float *Ws   = smf + OFF_WS;
    float *As   = smf + OFF_AS;
    float *Vs   = smf + OFF_V;
    unsigned long long *Wrd = (unsigned long long *)(smf + OFF_WRD);
    float *gs   = smf + OFF_GS;
    float *sc   = smf + OFF_SC;
    float *sb   = smf + OFF_SB;
    float *sbr  = smf + OFF_SBR;
    float *ss   = smf + OFF_SS;
    float *so   = smf + OFF_SO;
    float *ssuf = smf + OFF_SUF;
    float *sA   = smf + OFF_SA;
    float *csum = smf + OFF_CS;
    float *sred = smf + OFF_SRD;
    float *srr  = smf + OFF_SRR;

    const int tid  = threadIdx.x;
    const int bidx = blockIdx.x;
    const int lane = tid & 31, wid = tid >> 5;
    unsigned n = 0;

    Pipe pipe;
    pipe.mb0 = (uint32_t)__cvta_generic_to_shared(smf + OFF_MB);
    pipe.mb1 = pipe.mb0 + 8;
    pipe.as0 = (uint32_t)__cvta_generic_to_shared(As);
    pipe.as1 = pipe.as0 + CHB;
    pipe.ph  = 0;
    if (tid == 0) { mbar_init(pipe.mb0); mbar_init(pipe.mb1); }
    __syncthreads();

    // ---------------- prologue: transpose x[t] -> d_xT[t][k][b] -------------
    {
        float *tile = smf;  // 128x132 scratch inside Ws+As region (loaded later)
        for (int p = bidx; p < KSTART; p += GRIDN) {
#pragma unroll
            for (int q = 0; q < 16; ++q) {
                int idx = q * 1024 + tid * 4;
                int b = idx >> 7, k = idx & 127;
                float4 v = *(const float4 *)(x + ((size_t)p * 128 + b) * 128 + k);
                tile[b * 132 + k]     = v.x;
                tile[b * 132 + k + 1] = v.y;
                tile[b * 132 + k + 2] = v.z;
                tile[b * 132 + k + 3] = v.w;
            }
            __syncthreads();
#pragma unroll
            for (int q = 0; q < 16; ++q) {
                int idx = q * 1024 + tid * 4;
                int k = idx >> 7, b = idx & 127;
                float4 v = make_float4(tile[b * 132 + k], tile[(b + 1) * 132 + k],
                                       tile[(b + 2) * 132 + k], tile[(b + 3) * 132 + k]);
                *(float4 *)(d_xT + ((size_t)p * 128 + k) * 128 + b) = v;
            }
            __syncthreads();
        }
    }
    grid_sync(n);

    // ---------------- persistent loads ----------------
    for (int idx = tid; idx < 704 * 16; idx += NTHR) {
        int k = idx >> 4, cidx = idx & 15;
        int m = cidx >> 2, u = cidx & 3;
        int grow = m * 512 + bidx * 4 + u;
        Ws[idx] = (k < 192) ? Wih[(size_t)grow * 192 + k]
                            : Whh[(size_t)grow * 512 + (k - 192)];
    }
    for (int idx = tid; idx < 1024; idx += NTHR) {
        int c = idx >> 9, k = idx & 511;
        int nn = bidx + c * 128;
        float w = (nn < OCOLS) ? Wr[(size_t)nn * HID + k] : 0.0f;
        unsigned ub = __float_as_uint(w);
        Wrd[c * 512 + k] = (unsigned long long)ub | ((unsigned long long)ub << 32);
    }
    if (tid < 16) {
        int m = tid >> 2, u = tid & 3;
        int grow = m * 512 + bidx * 4 + u;
        sb[tid] = bih[grow] + bhh[grow];
    }
    if (tid < 2) {
        int nn = bidx + tid * 128;
        sbr[tid] = (nn < OCOLS) ? br[nn] : 0.0f;
    }
    for (int idx = tid; idx < 512; idx += NTHR) sc[idx] = 0.0f;
    for (int idx = tid; idx < 292; idx += NTHR) ss[idx] = 0.0f;
    for (int idx = tid; idx < 288; idx += NTHR) ssuf[idx] = 0.0f;  // scan of zeros
    if (tid < 32) csum[tid] = 0.0f;
    for (int idx = tid; idx < MAXT * STKD; idx += NTHR) Vs[idx] = 0.0f;
    __syncthreads();

    // GEMM thread mapping: 4 cols x 8 batches x 4-way k-split
    const int tx = tid & 3;            // col quad (cols 4tx..4tx+3)
    const int bo = (tid >> 2) & 15;    // batch octet (batches bo*8..bo*8+7)
    const int kq = tid >> 6;           // k-quarter within each 64-k chunk
    // readout mapping
    const int rc  = tid >> 7;            // col 0/1
    const int rks = (tid >> 5) & 3;      // k-split (16 kk each)
    const int rbq = tid & 31;            // batch quad

    unsigned long long acc0, acc1, acc2, acc3, acc4, acc5, acc6, acc7,
                       acc8, acc9, acc10, acc11, acc12, acc13, acc14, acc15;

#define ZERO_ACCS() \
    acc0 = acc1 = acc2 = acc3 = acc4 = acc5 = acc6 = acc7 = 0ull;   \
    acc8 = acc9 = acc10 = acc11 = acc12 = acc13 = acc14 = acc15 = 0ull;

// GEMM over one resident 64-k chunk: this thread covers its 16-k quarter.
#define GEMM_CHUNK(Ab, wrow)                                                  \
    {                                                                         \
        const float *Ab_ = (Ab) + kq * 16 * 128 + bo * 8;                     \
        const float *wp_ = Ws + (size_t)((wrow) + kq * 16) * 16 + tx * 4;     \
        _Pragma("unroll")                                                     \
        for (int kk = 0; kk < 16; ++kk) {                                     \
            ulonglong2 a01 = *(const ulonglong2 *)(Ab_ + kk * 128);           \
            ulonglong2 a23 = *(const ulonglong2 *)(Ab_ + kk * 128 + 4);       \
            float4 w = *(const float4 *)(wp_ + kk * 16);                      \
            unsigned long long w0, w1, w2, w3;                                \
            DUP2(w0, w.x); DUP2(w1, w.y); DUP2(w2, w.z); DUP2(w3, w.w);       \
            FFMA2(acc0,  a01.x, w0); FFMA2(acc1,  a01.y, w0);                 \
            FFMA2(acc2,  a23.x, w0); FFMA2(acc3,  a23.y, w0);                 \
            FFMA2(acc4,  a01.x, w1); FFMA2(acc5,  a01.y, w1);                 \
            FFMA2(acc6,  a23.x, w1); FFMA2(acc7,  a23.y, w1);                 \
            FFMA2(acc8,  a01.x, w2); FFMA2(acc9,  a01.y, w2);                 \
            FFMA2(acc10, a23.x, w2); FFMA2(acc11, a23.y, w2);                 \
            FFMA2(acc12, a01.x, w3); FFMA2(acc13, a01.y, w3);                 \
            FFMA2(acc14, a23.x, w3); FFMA2(acc15, a23.y, w3);                 \
        }                                                                     \
    }

// Parallel 4-way k-split reduce (stride-18, conflict-free) + bias -> gs -> cell.
#define EPILOGUE_CELL()                                                       \
    __syncthreads();                                                          \
    {                                                                         \
        unsigned long long *red_ = (unsigned long long *)As;                  \
        unsigned long long *d_ = red_ + (size_t)(kq * 64 + (tid & 63)) * RSTRIDE; \
        *(ulonglong2 *)(d_)      = make_ulonglong2(acc0,  acc1);              \
        *(ulonglong2 *)(d_ + 2)  = make_ulonglong2(acc2,  acc3);              \
        *(ulonglong2 *)(d_ + 4)  = make_ulonglong2(acc4,  acc5);              \
        *(ulonglong2 *)(d_ + 6)  = make_ulonglong2(acc6,  acc7);              \
        *(ulonglong2 *)(d_ + 8)  = make_ulonglong2(acc8,  acc9);              \
        *(ulonglong2 *)(d_ + 10) = make_ulonglong2(acc10, acc11);             \
        *(ulonglong2 *)(d_ + 12) = make_ulonglong2(acc12, acc13);             \
        *(ulonglong2 *)(d_ + 14) = make_ulonglong2(acc14, acc15);             \
        __syncthreads();                                                      \
        {                                                                     \
            const int pos2 = tid >> 2;                                        \
            const int i0   = (tid & 3) * 4;                                   \
            const unsigned long long *r0_ = red_ + (size_t)pos2 * RSTRIDE + i0;            \
            const unsigned long long *r1_ = red_ + (size_t)(64 + pos2) * RSTRIDE + i0;     \
            const unsigned long long *r2_ = red_ + (size_t)(128 + pos2) * RSTRIDE + i0;    \
            const unsigned long long *r3_ = red_ + (size_t)(192 + pos2) * RSTRIDE + i0;    \
            ulonglong2 pA = *(const ulonglong2 *)(r0_);                       \
            ulonglong2 pB = *(const ulonglong2 *)(r0_ + 2);                   \
            ulonglong2 qA = *(const ulonglong2 *)(r1_);                       \
            ulonglong2 qB = *(const ulonglong2 *)(r1_ + 2);                   \
            ADDF2(pA.x, qA.x); ADDF2(pA.y, qA.y);                             \
            ADDF2(pB.x, qB.x); ADDF2(pB.y, qB.y);                             \
            qA = *(const ulonglong2 *)(r2_);                                  \
            qB = *(const ulonglong2 *)(r2_ + 2);                              \
            ADDF2(pA.x, qA.x); ADDF2(pA.y, qA.y);                             \
            ADDF2(pB.x, qB.x); ADDF2(pB.y, qB.y);                             \
            qA = *(const ulonglong2 *)(r3_);                                  \
            qB = *(const ulonglong2 *)(r3_ + 2);                              \
            ADDF2(pA.x, qA.x); ADDF2(pA.y, qA.y);                             \
            ADDF2(pB.x, qB.x); ADDF2(pB.y, qB.y);                             \
            const int col_ = ((tid >> 2) & 3) * 4 + (tid & 3);                \
            const int bo_  = tid >> 4;                                        \
            float bs_ = sb[col_];                                             \
            float *gp_ = gs + col_ * 132 + bo_ * 8;                           \
            *(float4 *)gp_ = make_float4(                                     \
                __uint_as_float((unsigned)pA.x) + bs_,                        \
                __uint_as_float((unsigned)(pA.x >> 32)) + bs_,                \
                __uint_as_float((unsigned)pA.y) + bs_,                        \
                __uint_as_float((unsigned)(pA.y >> 32)) + bs_);               \
            *(float4 *)(gp_ + 4) = make_float4(                               \
                __uint_as_float((unsigned)pB.x) + bs_,                        \
                __uint_as_float((unsigned)(pB.x >> 32)) + bs_,                \
                __uint_as_float((unsigned)pB.y) + bs_,                        \
                __uint_as_float((unsigned)(pB.y >> 32)) + bs_);               \
        }                                                                     \
    }                                                                         \
    __syncthreads();                                                          \
    _Pragma("unroll")                                                         \
    for (int r = 0; r < 2; ++r) {                                             \
        int idx = tid + r * NTHR;                                             \
        int u = idx >> 7, bb = idx & 127;                                     \
        float gi = gs[u * 132 + bb];                                          \
        float gf = gs[(4 + u) * 132 + bb];                                    \
        float gg = gs[(8 + u) * 132 + bb];                                    \
        float go = gs[(12 + u) * 132 + bb];                                   \
        float c2 = sigf(gf) * sc[idx] + sigf(gi) * tanhf(gg);                 \
        sc[idx] = c2;                                                         \
        d_RH[(size_t)(64 + bidx * 4 + u) * 128 + bb] = sigf(go) * tanhf(c2);  \
    }

// Full-width suffix scan of ss -> ssuf, csum (used when no softmax runs).
#define SCAN_SS()                                                             \
    for (int cch = wid; cch < 9; cch += 8) {                                  \
        float v = ss[cch * 32 + lane];                                        \
        _Pragma("unroll")                                                     \
        for (int o = 1; o < 32; o <<= 1) {                                    \
            float tv = __shfl_down_sync(0xffffffffu, v, o);                   \
            if (lane + o < 32) v += tv;                                       \
        }                                                                     \
        ssuf[cch * 32 + lane] = v;                                            \
        if (lane == 0) csum[cch] = v;                                         \
    }                                                                         \
    __syncthreads();                                                          \
    if (wid == 0) {                                                           \
        float tv = (lane < 9) ? csum[lane] : 0.0f;                            \
        float vv = tv;                                                        \
        _Pragma("unroll")                                                     \
        for (int o = 1; o < 16; o <<= 1) {                                    \
            float sh = __shfl_down_sync(0xffffffffu, vv, o);                  \
            if (lane + o < 16) vv += sh;                                      \
        }                                                                     \
        if (lane < 9) csum[lane] = vv - tv;                                   \
    }

// Full-width log-softmax (used only on the last step; scratch csum).
#define SOFTMAX_OUT(tt)                                                       \
    {                                                                         \
        float v = (tid < INPD) ? so[STKD + tid] : -1e30f;                     \
        float m = v;                                                          \
        _Pragma("unroll")                                                     \
        for (int o = 16; o; o >>= 1)                                          \
            m = fmaxf(m, __shfl_xor_sync(0xffffffffu, m, o));                 \
        if (lane == 0) csum[wid] = m;                                         \
        __syncthreads();                                                      \
        float mm = csum[0];                                                   \
        _Pragma("unroll")                                                     \
        for (int w = 1; w < 8; ++w) mm = fmaxf(mm, csum[w]);                  \
        float e = (tid < INPD) ? expf(v - mm) : 0.0f;                         \
        _Pragma("unroll")                                                     \
        for (int o = 16; o; o >>= 1)                                          \
            e += __shfl_xor_sync(0xffffffffu, e, o);                          \
        if (lane == 0) csum[8 + wid] = e;                                     \
        __syncthreads();                                                      \
        float tot = 0.0f;                                                     \
        _Pragma("unroll")                                                     \
        for (int w = 0; w < 8; ++w) tot += csum[8 + w];                       \
        float ls = logf(tot);                                                 \
        if (tid < INPD)                                                       \
            out[(((size_t)((tt) - KSTART)) * BATCH + bidx) * INPD + tid] =    \
                v - mm - ls;                                                  \
        __syncthreads();                                                      \
    }

// Half-width softmax: warps 0-3 (tid<128), scratch sred[0..7], named bar 1.
#define SOFTMAX_HALF(tt)                                                      \
    {                                                                         \
        float v = so[STKD + tid];                                             \
        float m = v;                                                          \
        _Pragma("unroll")                                                     \
        for (int o = 16; o; o >>= 1)                                          \
            m = fmaxf(m, __shfl_xor_sync(0xffffffffu, m, o));                 \
        if (lane == 0) sred[wid] = m;                                         \
        BARN(1, 128);                                                         \
        float mm = fmaxf(fmaxf(sred[0], sred[1]), fmaxf(sred[2], sred[3]));   \
        float e = expf(v - mm);                                               \
        _Pragma("unroll")                                                     \
        for (int o = 16; o; o >>= 1)                                          \
            e += __shfl_xor_sync(0xffffffffu, e, o);                          \
        if (lane == 0) sred[4 + wid] = e;                                     \
        BARN(1, 128);                                                         \
        float tot = (sred[4] + sred[5]) + (sred[6] + sred[7]);                \
        float ls = logf(tot);                                                 \
        out[(((size_t)((tt) - KSTART)) * BATCH + bidx) * INPD + tid] =        \
            v - mm - ls;                                                      \
    }

// Half-width scan: warps 4-7, named bar 2; warp 4 does the chunk-total suffix.
#define SCAN_HALF()                                                           \
    {                                                                         \
        const int w4 = wid - 4;                                               \
        for (int cch = w4; cch < 9; cch += 4) {                               \
            float v = ss[cch * 32 + lane];                                    \
            _Pragma("unroll")                                                 \
            for (int o = 1; o < 32; o <<= 1) {                                \
                float tv = __shfl_down_sync(0xffffffffu, v, o);               \
                if (lane + o < 32) v += tv;                                   \
            }                                                                 \
            ssuf[cch * 32 + lane] = v;                                        \
            if (lane == 0) csum[cch] = v;                                     \
        }                                                                     \
        BARN(2, 128);                                                         \
        if (wid == 4) {                                                       \
            float tv = (lane < 9) ? csum[lane] : 0.0f;                        \
            float vv = tv;                                                    \
            _Pragma("unroll")                                                 \
            for (int o = 1; o < 16; o <<= 1) {                                \
                float sh = __shfl_down_sync(0xffffffffu, vv, o);              \
                if (lane + o < 16) vv += sh;                                  \
            }                                                                 \
            if (lane < 9) csum[lane] = vv - tv;                               \
        }                                                                     \
    }

    // ================= init: gates_0 = x_0 part only; cell -> h_0 ===========
    ZERO_ACCS()
    pipe.prefetch(0, d_xT, tid == 0);
    pipe.prefetch(1, d_xT + 64 * 128, tid == 0);
    pipe.wait(0);
    GEMM_CHUNK(As, 0)
    pipe.wait(1);
    GEMM_CHUNK(As + CHF, 64)
    EPILOGUE_CELL()
    grid_sync(n);

    // =========================== main time loop =============================
    for (int t = 0; t < NSTEPS; ++t) {
        const bool has_x = (t < 128);

        // ---------- I1: h gate chunks + fused readout ----------
        pipe.prefetch(0, d_RH + (size_t)64 * 128, tid == 0);  // h chunk 0, asap
        ZERO_ACCS()
        unsigned long long racc0 = 0ull, racc1 = 0ull;
#pragma unroll 1
        for (int ci = 0; ci < 8; ++ci) {
            if (ci + 1 < 8)
                pipe.prefetch((ci + 1) & 1,
                              d_RH + (size_t)(64 + (ci + 1) * 64) * 128, tid == 0);
            pipe.wait(ci & 1);
            const float *Ab = As + (ci & 1) * CHF;
            GEMM_CHUNK(Ab, 192 + ci * 64)
            {   // f32x2 readout over this h chunk
                const float *Ar = Ab + (rks * 16) * 128 + rbq * 4;
                const unsigned long long *wr = Wrd + rc * 512 + ci * 64 + rks * 16;
#pragma unroll
                for (int m = 0; m < 16; ++m) {
                    ulonglong2 a = *(const ulonglong2 *)(Ar + m * 128);
                    unsigned long long w = wr[m];
                    FFMA2(racc0, a.x, w);
                    FFMA2(racc1, a.y, w);
                }
            }
            if (ci < 7) __syncthreads();   // last-chunk sync subsumed below
        }
        // readout reduce + store o194 batch-major
        {
            float4 rv = make_float4(__uint_as_float((unsigned)racc0),
                                    __uint_as_float((unsigned)(racc0 >> 32)),
                                    __uint_as_float((unsigned)racc1),
                                    __uint_as_float((unsigned)(racc1 >> 32)));
            *(float4 *)(srr + rks * 256 + rc * 128 + rbq * 4) = rv;
        }
        __syncthreads();
        {
            int c = tid >> 7, b = tid & 127;
            int nn = bidx + c * 128;
            if (nn < OCOLS) {
                float o = srr[b + c * 128] + srr[256 + b + c * 128] +
                          srr[512 + b + c * 128] + srr[768 + b + c * 128] + sbr[c];
                d_o194[(size_t)b * OPAD + nn] = o;
            }
        }
        grid_sync(n);

        // ---------- I2: so-LDG hidden under x0 TMA+GEMM; then stack ---------
        const int b = bidx;
        if (has_x) {
            pipe.prefetch(0, d_xT + ((size_t)(t + 1) * 128) * 128, tid == 0);
            pipe.prefetch(1, d_xT + ((size_t)(t + 1) * 128 + 64) * 128, tid == 0);
        }
        float myo = 0.0f;
        if (tid < OCOLS) myo = d_o194[(size_t)b * OPAD + tid];   // LDG in flight
        if (has_x) {
            pipe.wait(0);
            GEMM_CHUNK(As, 0)          // x0 GEMM hides the so LDG latency
        }
        if (tid < OCOLS) so[tid] = myo;
        __syncthreads();

        if (tid < STKD) Vs[t * STKD + tid] = so[tid];
        float u_ = sigf(so[192]);
        float dd = sigf(so[193]);

        // sp/sA using PRECOMPUTED ssuf/csum (from previous I3 / init)
        for (int i = tid; i < MAXT; i += NTHR) {
            float si   = ss[i];
            float prod = ssuf[i] + csum[i >> 5] - si;
            float sp   = fmaxf(0.0f, si - fmaxf(0.0f, u_ - prod));
            if (i == t) sp = dd;
            float inner = fmaxf(0.0f, 1.0f - prod - sp);
            sA[i] = fminf(sp, inner);
            if (i <= t) ss[i] = sp;
        }
        __syncthreads();

        // r_t[d] = sum_{i<=t} A[i] * V[i][d]   (all smem, 4-way MLP)
        {
            const int dcol = tid & 63, q = tid >> 6;   // q 0..3, stride 4
            float a0 = 0.f, a1 = 0.f, a2 = 0.f, a3 = 0.f;
            int i = q;
            for (; i + 12 <= t; i += 16) {
                a0 = fmaf(sA[i],      Vs[i * 64 + dcol],        a0);
                a1 = fmaf(sA[i + 4],  Vs[(i + 4) * 64 + dcol],  a1);
                a2 = fmaf(sA[i + 8],  Vs[(i + 8) * 64 + dcol],  a2);
                a3 = fmaf(sA[i + 12], Vs[(i + 12) * 64 + dcol], a3);
            }
            for (; i <= t; i += 4)
                a0 = fmaf(sA[i], Vs[i * 64 + dcol], a0);
            sred[q * 64 + dcol] = (a0 + a1) + (a2 + a3);
        }
        __syncthreads();
        if (tid < STKD)
            d_RH[(size_t)tid * 128 + b] =
                sred[tid] + sred[64 + tid] + sred[128 + tid] + sred[192 + tid];

        if (t == NSTEPS - 1) {
            __syncthreads();
            SOFTMAX_OUT(t)           // last step's output (no I3 follows)
            grid_sync(n);
            break;
        }
        grid_sync(n);

        // ---------- I3: softmax||scan + x1 + r chunk + cell -----------------
        pipe.prefetch(0, d_RH, tid == 0);       // r chunk into buf0
        if (t >= KSTART) {
            if (wid < 4) { SOFTMAX_HALF(t) }    // warps 0-3, scratch sred
            else         { SCAN_HALF() }        // warps 4-7, ssuf/csum
        } else {
            SCAN_SS()                           // full-width scan (no softmax)
        }
        if (has_x) {
            pipe.wait(1);                       // x chunk 1 (issued in I2)
            GEMM_CHUNK(As + CHF, 64)
        }
        pipe.wait(0);                           // r chunk
        GEMM_CHUNK(As, 128)
        EPILOGUE_CELL()
        grid_sync(n);
    }
}

extern "C" void kernel_launch(void *const *d_in, const int *in_sizes, int n_in,
                              void *d_out, int out_size) {
    (void)in_sizes; (void)n_in; (void)out_size;
    const float *x   = (const float *)d_in[0];
    const float *Wih = (const float *)d_in[1];
    const float *bih = (const float *)d_in[2];
    const float *Whh = (const float *)d_in[3];
    const float *bhh = (const float *)d_in[4];
    const float *Wr  = (const float *)d_in[5];
    const float *br  = (const float *)d_in[6];
    float *out = (float *)d_out;

    cudaFuncSetAttribute(lstm_stack_kernel,
                         cudaFuncAttributeMaxDynamicSharedMemorySize, SMEMB);

    void *p;
    cudaGetSymbolAddress(&p, d_RH);  cudaMemsetAsync(p, 0, sizeof(float) * (64 + 512) * 128);
    cudaGetSymbolAddress(&p, g_bar); cudaMemsetAsync(p, 0, sizeof(unsigned));

    lstm_stack_kernel<<<GRIDN, NTHR, SMEMB>>>(x, Wih, bih, Whh, bhh, Wr, br, out);
}